// round 9
// baseline (speedup 1.0000x reference)
#include <cuda_runtime.h>

// MeshUnpool: out[b,f,t] = (1/occ[b,t]) * sum_e features[b,f,e] * group[b,e,t]
// group ~0.1%-dense 0/1 mask. Stream group once (384 MB) with ld.global.cv
// (R7 win: L1-bypass lifted 4.78->5.17 TB/s), record sparse hits, then
// warp-exclusive accumulation (no hot-path atomics).
//
// R9 = R8 geometry (TILE_T=32: full 128B lines per warp-load, UNROLL=10,
// 123 KB in-flight/SM, 0.85 waves) + the bounds guards R8 fatally dropped:
// 6000 % 32 != 0, so the last t-tile of each batch overhangs by 16 and must
// be predicated (R8 wrote OOB into the next batch's out region).

#define BB 4
#define NF 64
#define EE 4000
#define TT 6000

#define TILE_T 32
#define NLANE  (TILE_T / 4)        // 8 float4 lanes
#define NTHREADS 128
#define NSPLIT (NTHREADS / NLANE)  // 16 E-splits
#define EPT    (EE / NSPLIT)       // 250 rows per split
#define UNROLL 10                  // 25 outer iterations
#define NTILES ((TT + TILE_T - 1) / TILE_T)  // 188 -> grid 752
#define HITS_MAX 768               // expected ~128 hits/block

// 4 MB scratch for transposed features [B][E][NF].
__device__ __align__(16) float g_featT[BB * EE * NF];

__device__ __forceinline__ float4 ldcv_f4(const float4* p) {
    float4 v;
    asm volatile("ld.global.cv.v4.f32 {%0,%1,%2,%3}, [%4];"
                 : "=f"(v.x), "=f"(v.y), "=f"(v.z), "=f"(v.w)
                 : "l"(p));
    return v;
}

// ---------------------------------------------------------------------------
// Kernel 1: transpose features [B, NF, E] -> featT [B, E, NF]
// ---------------------------------------------------------------------------
__global__ void transpose_feat_kernel(const float* __restrict__ feat) {
    __shared__ float tile[32][33];
    const int b  = blockIdx.z;
    const int e0 = blockIdx.x * 32;
    const int f0 = blockIdx.y * 32;
    const int tx = threadIdx.x;   // 0..31
    const int ty = threadIdx.y;   // 0..7

#pragma unroll
    for (int j = 0; j < 32; j += 8)
        tile[ty + j][tx] = feat[((size_t)(b * NF + f0 + ty + j)) * EE + e0 + tx];
    __syncthreads();
#pragma unroll
    for (int j = 0; j < 32; j += 8)
        g_featT[((size_t)b * EE + (e0 + ty + j)) * NF + f0 + tx] = tile[tx][ty + j];
}

// ---------------------------------------------------------------------------
// Kernel 2: stream + two-phase sparse accumulate
// ---------------------------------------------------------------------------
__global__ void __launch_bounds__(NTHREADS, 6)
unpool_kernel(const float* __restrict__ group,
              const float* __restrict__ occ,
              float* __restrict__ out) {
    __shared__ float acc[TILE_T][NF + 1];   // bank(acc[tt][f]) = (tt+f)%32
    __shared__ float inv_occ[TILE_T];
    __shared__ int   hits[HITS_MAX];        // packed (e << 8) | tt
    __shared__ int   nhits;

    const int b    = blockIdx.x / NTILES;
    const int tile = blockIdx.x % NTILES;
    const int t0   = tile * TILE_T;
    const int tid  = threadIdx.x;

    // init (guarded: last tile of each batch overhangs, 6000 % 32 = 16)
    for (int i = tid; i < TILE_T * (NF + 1); i += NTHREADS)
        (&acc[0][0])[i] = 0.0f;
    if (tid < TILE_T) {
        const int t = t0 + tid;
        inv_occ[tid] = (t < TT) ? (1.0f / occ[(size_t)b * TT + t]) : 0.0f;
    }
    if (tid == 0) nhits = 0;
    __syncthreads();

    // ---- Phase A: stream group, record nonzero coordinates ----
    const int lane4  = tid & (NLANE - 1);   // 0..7: which float4 of the tile
    const int esplit = tid / NLANE;         // 0..15: which E-split
    const int tloc   = lane4 * 4;
    const bool valid = (t0 + tloc) < TT;    // TT % 4 == 0: float4-granular

    if (valid) {
        const float* gbase = group + (size_t)b * EE * TT + t0 + tloc;
        const int e_begin = esplit * EPT;
        for (int it = 0; it < EPT / UNROLL; it++) {
            const int eb = e_begin + it * UNROLL;
            float4 v[UNROLL];
#pragma unroll
            for (int u = 0; u < UNROLL; u++)
                v[u] = ldcv_f4(reinterpret_cast<const float4*>(
                    gbase + (size_t)(eb + u) * TT));
            unsigned any = 0;
#pragma unroll
            for (int u = 0; u < UNROLL; u++)
                any |= __float_as_uint(v[u].x) | __float_as_uint(v[u].y) |
                       __float_as_uint(v[u].z) | __float_as_uint(v[u].w);
            if (any) {  // rare (~4% of thread-batches)
#pragma unroll
                for (int u = 0; u < UNROLL; u++) {
                    const float c[4] = {v[u].x, v[u].y, v[u].z, v[u].w};
#pragma unroll
                    for (int k = 0; k < 4; k++) {
                        if (__float_as_uint(c[k])) {
                            int idx = atomicAdd(&nhits, 1);
                            if (idx < HITS_MAX)
                                hits[idx] = ((eb + u) << 8) | (tloc + k);
                        }
                    }
                }
            }
        }
    }
    __syncthreads();

    // ---- Phase B: warp w exclusively owns tt in [8w, 8w+8) ----
    {
        const int wid  = tid >> 5;          // 0..3
        const int lane = tid & 31;
        const int n = (nhits < HITS_MAX) ? nhits : HITS_MAX;
        for (int i = 0; i < n; i++) {
            const int h  = hits[i];         // LDS broadcast
            const int tt = h & 0xFF;
            if ((tt >> 3) == wid) {
                const int e = h >> 8;
                const float* col = g_featT + ((size_t)b * EE + e) * NF;
                // group values at hits are exactly 1.0
                acc[tt][lane]      += col[lane];
                acc[tt][lane + 32] += col[lane + 32];
            }
        }
    }
    __syncthreads();

    // ---- writeout: out[b, f, t0+tt] = acc[tt][f] * inv_occ[tt] ----
    for (int i = tid; i < NF * TILE_T; i += NTHREADS) {
        const int f  = i / TILE_T;
        const int tt = i % TILE_T;
        const int t  = t0 + tt;
        if (t < TT)
            out[((size_t)b * NF + f) * TT + t] = acc[tt][f] * inv_occ[tt];
    }
}

extern "C" void kernel_launch(void* const* d_in, const int* in_sizes, int n_in,
                              void* d_out, int out_size) {
    const float* features = (const float*)d_in[0];   // [B, NF, E]
    const float* group    = (const float*)d_in[1];   // [B, E, T]
    const float* occ      = (const float*)d_in[2];   // [B, T]
    float* out = (float*)d_out;                      // [B, NF, T]

    dim3 tgrid(EE / 32, NF / 32, BB);
    dim3 tblk(32, 8);
    transpose_feat_kernel<<<tgrid, tblk>>>(features);

    unpool_kernel<<<BB * NTILES, NTHREADS>>>(group, occ, out);
}